// round 13
// baseline (speedup 1.0000x reference)
#include <cuda_runtime.h>
#include <cuda_bf16.h>
#include <cstdint>

#define Nn 4096
#define Bb 4
#define Cc 128
#define Hh 8
#define Vv 16
#define HV 128

// ---------------- static device scratch ------------------------------------
__device__ __align__(16) __nv_bfloat16 g_vh[(size_t)Hh * 64 * Nn];  // value hi plane [h][c2][j]
__device__ __align__(16) __nv_bfloat16 g_vl[(size_t)Hh * 64 * Nn];  // value lo plane
__device__ float g_rowstats[3 * Nn];  // [0..N) d_lo, [N..2N) d_hi, [2N..3N) d_min

__device__ __forceinline__ float read_pct(const int* p) {
    if (!p) return 64.0f;
    int v = *p;
    if (v >= 0 && v <= 100) return (float)v;
    float f = __int_as_float(v);
    if (f >= 0.0f && f <= 100.0f) return f;
    return 64.0f;
}

// warp-level bf16 tensor-core mma (sm_80+ PTX, valid on base sm_103 target)
#define MMA_BF16(c0, c1, c2, c3, a0, a1, a2, a3, b0, b1)                      \
    asm volatile(                                                             \
        "mma.sync.aligned.m16n8k16.row.col.f32.bf16.bf16.f32 "                \
        "{%0,%1,%2,%3}, {%4,%5,%6,%7}, {%8,%9}, {%0,%1,%2,%3};"               \
        : "+f"(c0), "+f"(c1), "+f"(c2), "+f"(c3)                              \
        : "r"(a0), "r"(a1), "r"(a2), "r"(a3), "r"(b0), "r"(b1))

// pack {lo, hi} floats -> bf16x2 (round-to-nearest); first PTX src -> high half
#define PACK_BF16X2(d, flo, fhi) \
    asm("cvt.rn.bf16x2.f32 %0, %1, %2;" : "=r"(d) : "f"(fhi), "f"(flo))

// {a.hi16 -> low half, b.hi16 -> high half}: truncation-split hi pack
__device__ __forceinline__ uint32_t prmt7632(uint32_t a, uint32_t b) {
    uint32_t d;
    asm("prmt.b32 %0, %1, %2, 0x7632;" : "=r"(d) : "r"(a), "r"(b));
    return d;
}

// ---------------------------------------------------------------------------
// Kernel 1: per row of dist: rank-k0 order statistic (radix select, exact,
// tie-safe on non-negative float bit patterns), rank-k0+1 from one extra
// pass, plus row min.  (Unchanged — passing at 58us.)
// ---------------------------------------------------------------------------
__global__ void __launch_bounds__(256, 1) rowstats_kernel(
    const float* __restrict__ dist, const int* __restrict__ locp) {
    __shared__ unsigned keys[Nn];
    __shared__ unsigned hist[256];
    __shared__ unsigned wsums[8];
    __shared__ unsigned sb[2];
    __shared__ float smin[256];
    __shared__ unsigned s_cntLE;
    __shared__ unsigned s_minAbove;

    const int row = blockIdx.x;
    const int t = threadIdx.x;

    const float* rp = dist + (size_t)row * Nn;
    float mn = 3.4e38f;
    for (int i = t; i < Nn; i += 256) {
        float v = rp[i];
        keys[i] = __float_as_uint(v);
        mn = fminf(mn, v);
    }
    smin[t] = mn;
    if (t == 0) { s_cntLE = 0u; s_minAbove = 0xFFFFFFFFu; }
    __syncthreads();
    for (int s = 128; s > 0; s >>= 1) {
        if (t < s) smin[t] = fminf(smin[t], smin[t + s]);
        __syncthreads();
    }

    float pct = read_pct(locp);
    float q = pct / 100.0f;
    float fidx = q * (float)(Nn - 1);
    int k0 = (int)floorf(fidx);
    if (k0 < 0) k0 = 0;
    if (k0 > Nn - 1) k0 = Nn - 1;

    int k = k0;
    unsigned prefix = 0u, pmask = 0u;
    for (int shift = 24; shift >= 0; shift -= 8) {
        hist[t] = 0u;
        __syncthreads();
        for (int i = t; i < Nn; i += 256) {
            unsigned key = keys[i];
            if ((key & pmask) == prefix)
                atomicAdd(&hist[(key >> shift) & 255u], 1u);
        }
        __syncthreads();
        unsigned c = hist[t];
        unsigned v = c;
        #pragma unroll
        for (int o = 1; o < 32; o <<= 1) {
            unsigned u = __shfl_up_sync(0xffffffffu, v, o);
            if ((t & 31) >= o) v += u;
        }
        if ((t & 31) == 31) wsums[t >> 5] = v;
        __syncthreads();
        if (t < 8) {
            unsigned w = wsums[t];
            #pragma unroll
            for (int o = 1; o < 8; o <<= 1) {
                unsigned u = __shfl_up_sync(0xffu, w, o);
                if (t >= o) w += u;
            }
            wsums[t] = w;
        }
        __syncthreads();
        unsigned incl = v + ((t >= 32) ? wsums[(t >> 5) - 1] : 0u);
        unsigned excl = incl - c;
        if ((unsigned)k >= excl && (unsigned)k < incl) {
            sb[0] = (unsigned)t;
            sb[1] = excl;
        }
        __syncthreads();
        prefix |= sb[0] << shift;
        pmask |= 0xFFu << shift;
        k -= (int)sb[1];
        __syncthreads();
    }
    const unsigned val0 = prefix;

    {
        unsigned lcnt = 0u, lmin = 0xFFFFFFFFu;
        for (int i = t; i < Nn; i += 256) {
            unsigned key = keys[i];
            if (key <= val0) lcnt++;
            else lmin = min(lmin, key);
        }
        #pragma unroll
        for (int o = 16; o > 0; o >>= 1) {
            lcnt += __shfl_down_sync(0xffffffffu, lcnt, o);
            lmin = min(lmin, __shfl_down_sync(0xffffffffu, lmin, o));
        }
        if ((t & 31) == 0) {
            atomicAdd(&s_cntLE, lcnt);
            atomicMin(&s_minAbove, lmin);
        }
    }
    __syncthreads();

    if (t == 0) {
        unsigned val1;
        int k1 = (k0 + 1 < Nn) ? (k0 + 1) : (Nn - 1);
        if (k1 == k0 || (unsigned)k1 < s_cntLE) val1 = val0;
        else val1 = s_minAbove;
        g_rowstats[row] = __uint_as_float(val0);
        g_rowstats[Nn + row] = __uint_as_float(val1);
        g_rowstats[2 * Nn + row] = smin[0];
    }
}

// ---------------------------------------------------------------------------
// Kernel 2: value[h][j][c2] = sum_c inputs[b,j,c]*weight[h,c,v]  (c2=b*16+v),
// split into bf16 hi/lo and written TRANSPOSED: g_vh/g_vl[h][c2][j].
// ---------------------------------------------------------------------------
__global__ void __launch_bounds__(512, 1) value_kernel(
    const float* __restrict__ inputs, const float* __restrict__ weight) {
    __shared__ float wsm[Cc * Vv];                 // 8KB
    __shared__ __nv_bfloat16 shT[64][72];          // [c2][j] hi
    __shared__ __nv_bfloat16 slT[64][72];          // [c2][j] lo
    const int h = blockIdx.y;
    const int j0 = blockIdx.x * 64;
    const int tid = threadIdx.x;

    for (int e = tid; e < Cc * Vv; e += 512) wsm[e] = weight[h * (Cc * Vv) + e];
    __syncthreads();

    const int c2 = tid & 63;
    const int jj = tid >> 6;  // 0..7
    const int b = c2 >> 4;
    const int v = c2 & 15;

    #pragma unroll
    for (int l = 0; l < 8; l++) {
        int jl = jj + l * 8;
        int j = j0 + jl;
        const float4* ip = (const float4*)(inputs + ((size_t)b * Nn + j) * Cc);
        float acc = 0.0f;
        #pragma unroll
        for (int c4 = 0; c4 < Cc / 4; c4++) {
            float4 x = ip[c4];
            acc += x.x * wsm[(c4 * 4 + 0) * Vv + v];
            acc += x.y * wsm[(c4 * 4 + 1) * Vv + v];
            acc += x.z * wsm[(c4 * 4 + 2) * Vv + v];
            acc += x.w * wsm[(c4 * 4 + 3) * Vv + v];
        }
        __nv_bfloat16 hi = __float2bfloat16(acc);
        __nv_bfloat16 lo = __float2bfloat16(acc - __bfloat162float(hi));
        shT[c2][jl] = hi;
        slT[c2][jl] = lo;
    }
    __syncthreads();

    const int c2r = tid >> 3;  // 0..63
    const int seg = tid & 7;   // 0..7
    uint4 vh = *(const uint4*)&shT[c2r][seg * 8];
    uint4 vl = *(const uint4*)&slT[c2r][seg * 8];
    size_t off = ((size_t)h * 64 + c2r) * Nn + j0 + seg * 8;
    *(uint4*)(g_vh + off) = vh;
    *(uint4*)(g_vl + off) = vl;
}

// ---------------------------------------------------------------------------
// Kernel 3: fused masked-softmax attention via mma.sync bf16 (split-2, 3
// products hh+hl+lh). W (A operand) fragments generated DIRECTLY IN REGISTERS
// from dist — no W smem, no producer barrier. V tiles (hi/lo) double-buffered
// in smem; one __syncthreads per tile. Row softmax sums: per-lane partials
// over the lane's 16 cols/row, quad-shuffle reduced once at the end.
// ---------------------------------------------------------------------------
#define VPITCH 144            // 72 bf16 per V row
#define VBUF 18432            // one buffer: hi(9216) + lo(9216)

__global__ void __launch_bounds__(256, 2) att_kernel(
    const float* __restrict__ dist, const float* __restrict__ r_in,
    const int* __restrict__ locp, float* __restrict__ out) {
    __shared__ __align__(16) char smem[2 * VBUF];
    const int tid = threadIdx.x;
    const int wid = tid >> 5;
    const int lid = tid & 31;
    const int h = blockIdx.y;
    const int i0 = blockIdx.x * 128;

    // th = tan((pi/4)*(1+sin r)) with fp32-quantized argument (matches ref)
    float th;
    {
        float sr = sinf(r_in[h]);
        float z = 0.78539816339744831f * (1.0f + sr);
        th = (float)tan((double)z);
    }

    const int g = lid >> 2;   // 0..7
    const int tq = lid & 3;   // 0..3
    const int rA = i0 + 16 * wid + g;   // global rows this lane covers
    const int rB = rA + 8;

    float mA, sA, mB, sB;
    {
        float pct = read_pct(locp);
        float q = pct / 100.0f;
        float fidx = q * (float)(Nn - 1);
        float frac = fidx - floorf(fidx);
        float lw = 1.0f - frac;
        mA = (th * g_rowstats[rA]) * lw + (th * g_rowstats[Nn + rA]) * frac;
        sA = th * g_rowstats[2 * Nn + rA];
        mB = (th * g_rowstats[rB]) * lw + (th * g_rowstats[Nn + rB]) * frac;
        sB = th * g_rowstats[2 * Nn + rB];
    }

    const float* dA = dist + (size_t)rA * Nn;
    const float* dB = dist + (size_t)rB * Nn;
    const __nv_bfloat16* vhp = g_vh + (size_t)h * 64 * Nn;
    const __nv_bfloat16* vlp = g_vl + (size_t)h * 64 * Nn;

    // V staging: 4 threads per row, 16 elements (2x uint4) per plane each
    const int vn = tid >> 2;
    const int vseg = tid & 3;
    const __nv_bfloat16* vsrcH = vhp + (size_t)vn * Nn + vseg * 16;
    const __nv_bfloat16* vsrcL = vlp + (size_t)vn * Nn + vseg * 16;
    char* vdst0 = smem + vn * VPITCH + vseg * 32;  // + buf*VBUF (+9216 for lo)

    float acc[8][4];
    #pragma unroll
    for (int nt = 0; nt < 8; nt++)
        #pragma unroll
        for (int c = 0; c < 4; c++) acc[nt][c] = 0.0f;
    float rowaccA = 0.0f, rowaccB = 0.0f;

    // prologue: load V tile 0 into buffer 0
    {
        uint4 h0 = *(const uint4*)(vsrcH);
        uint4 h1 = *(const uint4*)(vsrcH + 8);
        uint4 l0 = *(const uint4*)(vsrcL);
        uint4 l1 = *(const uint4*)(vsrcL + 8);
        *(uint4*)(vdst0) = h0;
        *(uint4*)(vdst0 + 16) = h1;
        *(uint4*)(vdst0 + 9216) = l0;
        *(uint4*)(vdst0 + 9216 + 16) = l1;
    }
    __syncthreads();

    for (int t = 0; t < Nn / 64; t++) {
        const int j0 = t * 64;
        const int cur = t & 1;
        const char* bufC = smem + cur * VBUF;

        // prefetch next V tile (regs)
        uint4 nh0, nh1, nl0, nl1;
        if (t < Nn / 64 - 1) {
            nh0 = *(const uint4*)(vsrcH + j0 + 64);
            nh1 = *(const uint4*)(vsrcH + j0 + 64 + 8);
            nl0 = *(const uint4*)(vsrcL + j0 + 64);
            nl1 = *(const uint4*)(vsrcL + j0 + 64 + 8);
        }

        // hoist all dist loads for this tile (MLP 16)
        float2 xA0[4], xA8[4], xB0[4], xB8[4];
        #pragma unroll
        for (int ks = 0; ks < 4; ks++) {
            int cb = j0 + ks * 16 + 2 * tq;
            xA0[ks] = *(const float2*)(dA + cb);
            xA8[ks] = *(const float2*)(dA + cb + 8);
            xB0[ks] = *(const float2*)(dB + cb);
            xB8[ks] = *(const float2*)(dB + cb + 8);
        }

        // generate A fragments (hi via truncation split, lo packed RN)
        uint32_t ah[4][4], al[4][4];
        #pragma unroll
        for (int ks = 0; ks < 4; ks++) {
            float sd;
            sd = th * xA0[ks].x; float wA0 = (sd <= mA) ? __expf(sA - sd) : 0.0f;
            sd = th * xA0[ks].y; float wA1 = (sd <= mA) ? __expf(sA - sd) : 0.0f;
            sd = th * xA8[ks].x; float wA8 = (sd <= mA) ? __expf(sA - sd) : 0.0f;
            sd = th * xA8[ks].y; float wA9 = (sd <= mA) ? __expf(sA - sd) : 0.0f;
            sd = th * xB0[ks].x; float wB0 = (sd <= mB) ? __expf(sB - sd) : 0.0f;
            sd = th * xB0[ks].y; float wB1 = (sd <= mB) ? __expf(sB - sd) : 0.0f;
            sd = th * xB8[ks].x; float wB8 = (sd <= mB) ? __expf(sB - sd) : 0.0f;
            sd = th * xB8[ks].y; float wB9 = (sd <= mB) ? __expf(sB - sd) : 0.0f;
            rowaccA += (wA0 + wA1) + (wA8 + wA9);
            rowaccB += (wB0 + wB1) + (wB8 + wB9);
            uint32_t uA0 = __float_as_uint(wA0), uA1 = __float_as_uint(wA1);
            uint32_t uA8 = __float_as_uint(wA8), uA9 = __float_as_uint(wA9);
            uint32_t uB0 = __float_as_uint(wB0), uB1 = __float_as_uint(wB1);
            uint32_t uB8 = __float_as_uint(wB8), uB9 = __float_as_uint(wB9);
            ah[ks][0] = prmt7632(uA0, uA1);   // {A[g][2tq], A[g][2tq+1]}
            ah[ks][1] = prmt7632(uB0, uB1);   // row g+8
            ah[ks][2] = prmt7632(uA8, uA9);   // k+8
            ah[ks][3] = prmt7632(uB8, uB9);
            float lA0 = wA0 - __uint_as_float(uA0 & 0xFFFF0000u);
            float lA1 = wA1 - __uint_as_float(uA1 & 0xFFFF0000u);
            float lA8 = wA8 - __uint_as_float(uA8 & 0xFFFF0000u);
            float lA9 = wA9 - __uint_as_float(uA9 & 0xFFFF0000u);
            float lB0 = wB0 - __uint_as_float(uB0 & 0xFFFF0000u);
            float lB1 = wB1 - __uint_as_float(uB1 & 0xFFFF0000u);
            float lB8 = wB8 - __uint_as_float(uB8 & 0xFFFF0000u);
            float lB9 = wB9 - __uint_as_float(uB9 & 0xFFFF0000u);
            PACK_BF16X2(al[ks][0], lA0, lA1);
            PACK_BF16X2(al[ks][1], lB0, lB1);
            PACK_BF16X2(al[ks][2], lA8, lA9);
            PACK_BF16X2(al[ks][3], lB8, lB9);
        }

        // store next V tile into the other buffer (mma below reads bufC)
        if (t < Nn / 64 - 1) {
            char* vdst = vdst0 + (1 - cur) * VBUF;
            *(uint4*)(vdst) = nh0;
            *(uint4*)(vdst + 16) = nh1;
            *(uint4*)(vdst + 9216) = nl0;
            *(uint4*)(vdst + 9216 + 16) = nl1;
        }

        // mma sweep: 4 k-steps x 8 n-tiles x 3 products
        #pragma unroll
        for (int ks = 0; ks < 4; ks++) {
            const uint32_t kb = (uint32_t)(ks * 16 + 2 * tq) * 2;
            #pragma unroll
            for (int nt = 0; nt < 8; nt++) {
                const uint32_t boff = (uint32_t)(8 * nt + g) * VPITCH + kb;
                uint32_t bh0 = *(const uint32_t*)(bufC + boff);
                uint32_t bh1 = *(const uint32_t*)(bufC + boff + 16);
                uint32_t bl0 = *(const uint32_t*)(bufC + 9216 + boff);
                uint32_t bl1 = *(const uint32_t*)(bufC + 9216 + boff + 16);
                MMA_BF16(acc[nt][0], acc[nt][1], acc[nt][2], acc[nt][3],
                         ah[ks][0], ah[ks][1], ah[ks][2], ah[ks][3], bh0, bh1);
                MMA_BF16(acc[nt][0], acc[nt][1], acc[nt][2], acc[nt][3],
                         ah[ks][0], ah[ks][1], ah[ks][2], ah[ks][3], bl0, bl1);
                MMA_BF16(acc[nt][0], acc[nt][1], acc[nt][2], acc[nt][3],
                         al[ks][0], al[ks][1], al[ks][2], al[ks][3], bh0, bh1);
            }
        }
        __syncthreads();
    }

    // quad reduce row sums (lanes tq=0..3 share rows rA, rB)
    rowaccA += __shfl_xor_sync(0xffffffffu, rowaccA, 1);
    rowaccA += __shfl_xor_sync(0xffffffffu, rowaccA, 2);
    rowaccB += __shfl_xor_sync(0xffffffffu, rowaccB, 1);
    rowaccB += __shfl_xor_sync(0xffffffffu, rowaccB, 2);
    const float invA = 1.0f / rowaccA;
    const float invB = 1.0f / rowaccB;

    // epilogue: normalize, exact gelu, write
    #pragma unroll
    for (int nt = 0; nt < 8; nt++) {
        const int col = nt * 8 + 2 * tq;
        const int b = col >> 4;
        const int v = col & 15;
        float x;
        float2 o0, o1;
        x = acc[nt][0] * invA; o0.x = 0.5f * x * (1.0f + erff(x * 0.70710678118654752f));
        x = acc[nt][1] * invA; o0.y = 0.5f * x * (1.0f + erff(x * 0.70710678118654752f));
        x = acc[nt][2] * invB; o1.x = 0.5f * x * (1.0f + erff(x * 0.70710678118654752f));
        x = acc[nt][3] * invB; o1.y = 0.5f * x * (1.0f + erff(x * 0.70710678118654752f));
        *(float2*)(&out[((size_t)b * Nn + rA) * HV + h * Vv + v]) = o0;
        *(float2*)(&out[((size_t)b * Nn + rB) * HV + h * Vv + v]) = o1;
    }
}

extern "C" void kernel_launch(void* const* d_in, const int* in_sizes, int n_in,
                              void* d_out, int out_size) {
    const float* inputs = (const float*)d_in[0];
    const float* dist   = (const float*)d_in[1];
    const float* r      = (const float*)d_in[2];
    const float* weight = (const float*)d_in[3];
    const int*   locp   = (n_in > 4) ? (const int*)d_in[4] : nullptr;
    float* out = (float*)d_out;
    (void)in_sizes; (void)out_size;

    rowstats_kernel<<<Nn, 256>>>(dist, locp);
    value_kernel<<<dim3(Nn / 64, Hh), 512>>>(inputs, weight);
    att_kernel<<<dim3(Nn / 128, Hh), 256>>>(dist, r, locp, out);
}